// round 2
// baseline (speedup 1.0000x reference)
#include <cuda_runtime.h>
#include <math.h>

#define NN   50000
#define EE   400000
#define TT   8
#define CINN 16
#define CH   32
#define FF   256
#define GG   64
#define ENDW 128
#define EPSF 1e-5f

// ---------------- scratch (device globals; no allocation) ----------------
__device__ float  g_x[NN*FF];
__device__ float  g_h[NN*FF];
__device__ float  g_gm[NN*FF];
__device__ float  g_agg[NN*FF];
__device__ float  g_dinv[NN];
__device__ int    g_indeg[NN];
__device__ int    g_rowptr[NN+1];
__device__ int    g_cursor[NN];
__device__ int    g_cols[EE];
__device__ float  g_wsrc[EE];
__device__ int    g_bsum[64];
__device__ double g_sum[FF];
__device__ double g_sumsq[FF];
__device__ float  g_scale[FF];
__device__ float  g_shift[FF];
__device__ float  g_coloff[FF];
__device__ float    g_psum[GG*CH];
__device__ unsigned g_pmax[GG*CH];
__device__ int      g_pcnt[GG];
__device__ float  g_m1[GG*ENDW];
__device__ float  g_m2[GG*64];

__device__ __forceinline__ unsigned fmap(float v) {
    unsigned u = __float_as_uint(v);
    return (u & 0x80000000u) ? ~u : (u | 0x80000000u);
}
__device__ __forceinline__ float funmap(unsigned u) {
    return (u & 0x80000000u) ? __uint_as_float(u & 0x7fffffffu) : __uint_as_float(~u);
}

// ---------------- input conv (1x1, CIN=16 -> C=32) ----------------
__global__ __launch_bounds__(256) void k_inconv(const float* __restrict__ X,
                                                const float* __restrict__ Wi,
                                                const float* __restrict__ bi) {
    __shared__ float xs[CINN*TT];
    __shared__ float wsh[CH*CINN];
    __shared__ float bsh[CH];
    int n = blockIdx.x, tid = threadIdx.x;
    if (tid < CINN*TT) xs[tid] = X[n*CINN*TT + tid];
    if (tid < CH) bsh[tid] = bi[tid];
    for (int i = tid; i < CH*CINN; i += 256) wsh[i] = Wi[i];
    __syncthreads();
    int c = tid >> 3, t = tid & 7;
    float a = bsh[c];
#pragma unroll
    for (int ci = 0; ci < CINN; ci++) a = fmaf(wsh[c*CINN+ci], xs[ci*TT+t], a);
    g_x[n*FF + tid] = a;
}

// ---------------- degree / CSR build ----------------
__global__ void k_zero_indeg() {
    int i = blockIdx.x*blockDim.x + threadIdx.x;
    if (i < NN) g_indeg[i] = 0;
}
__global__ void k_count(const int* __restrict__ dst) {
    int e = blockIdx.x*blockDim.x + threadIdx.x;
    if (e < EE) atomicAdd(&g_indeg[dst[e]], 1);
}
__global__ void k_dinv() {
    int i = blockIdx.x*blockDim.x + threadIdx.x;
    if (i < NN) g_dinv[i] = rsqrtf(1.0f + (float)g_indeg[i]);
}
__global__ __launch_bounds__(1024) void k_scanA() {
    __shared__ int sh[1024];
    int i = blockIdx.x*1024 + threadIdx.x;
    int v = (i < NN) ? g_indeg[i] : 0;
    sh[threadIdx.x] = v;
    __syncthreads();
    for (int off = 1; off < 1024; off <<= 1) {
        int t = (threadIdx.x >= off) ? sh[threadIdx.x-off] : 0;
        __syncthreads();
        sh[threadIdx.x] += t;
        __syncthreads();
    }
    if (i < NN) g_rowptr[i] = sh[threadIdx.x] - v;   // exclusive, block-local
    if (threadIdx.x == 1023) g_bsum[blockIdx.x] = sh[1023];
}
__global__ void k_scanB(int nblk) {
    int acc = 0;
    for (int b = 0; b < nblk; b++) { int t = g_bsum[b]; g_bsum[b] = acc; acc += t; }
    g_rowptr[NN] = acc;
}
__global__ void k_scanC() {
    int i = blockIdx.x*blockDim.x + threadIdx.x;
    if (i < NN) {
        int v = g_rowptr[i] + g_bsum[i >> 10];
        g_rowptr[i] = v;
        g_cursor[i] = v;
    }
}
__global__ void k_fill(const int* __restrict__ src, const int* __restrict__ dst) {
    int e = blockIdx.x*blockDim.x + threadIdx.x;
    if (e < EE) {
        int d = dst[e];
        int p = atomicAdd(&g_cursor[d], 1);
        int s = src[e];
        g_cols[p] = s;
        g_wsrc[p] = g_dinv[s];
    }
}

// ---------------- gated conv (C=32->32, k=3, pad=1), 8 nodes/block ----------------
__global__ __launch_bounds__(256) void k_gated(int src_sel, int use_affine,
                                               const float* __restrict__ W3,
                                               const float* __restrict__ b3) {
    __shared__ float ws[9216];       // ws[(cc*3+k)*96 + conv*32 + c]
    __shared__ float xs[8*330];      // [node][cc*10 + 1+t], pads at 0 and 9
    __shared__ float bsh[96];
    const float* in = src_sel ? g_agg : g_x;
    int tid = threadIdx.x;
    for (int i = tid; i < 9216; i += 256) {
        int k = i % 3, cc = (i/3) & 31, c = (i/96) & 31, conv = i / 3072;
        ws[(cc*3+k)*96 + conv*32 + c] = W3[i];
    }
    if (tid < 96) bsh[tid] = b3[tid];
    {
        int nb = tid >> 5, cc = tid & 31;
        xs[nb*330 + cc*10]     = 0.f;
        xs[nb*330 + cc*10 + 9] = 0.f;
    }
    int n0 = blockIdx.x * 8;
    for (int i = tid; i < 8*FF; i += 256) {
        int nb = i >> 8, f = i & 255;
        float v = in[(n0+nb)*FF + f];
        if (use_affine) v = fmaf(v, g_scale[f], g_shift[f]);
        xs[nb*330 + (f>>3)*10 + 1 + (f&7)] = v;
    }
    __syncthreads();
    int tx = tid & 7, c = tid >> 3;
    float aP[8], aQ[8], aR[8];
#pragma unroll
    for (int j = 0; j < 8; j++) { aP[j] = 0.f; aQ[j] = 0.f; aR[j] = 0.f; }
    const float* xb = &xs[tx*330];
    for (int cc = 0; cc < 32; cc++) {
        float xr[10];
#pragma unroll
        for (int m = 0; m < 10; m++) xr[m] = xb[cc*10+m];
#pragma unroll
        for (int k = 0; k < 3; k++) {
            int kk = (cc*3+k)*96;
            float wP = ws[kk + c];
            float wQ = ws[kk + 32 + c];
            float wR = ws[kk + 64 + c];
#pragma unroll
            for (int j = 0; j < 8; j++) {
                aP[j] = fmaf(wP, xr[j+k], aP[j]);
                aQ[j] = fmaf(wQ, xr[j+k], aQ[j]);
                aR[j] = fmaf(wR, xr[j+k], aR[j]);
            }
        }
    }
    float bP = bsh[c], bQ = bsh[32+c], bR = bsh[64+c];
    float o[8];
#pragma unroll
    for (int j = 0; j < 8; j++) {
        float p = aP[j] + bP;
        float q = aQ[j] + bQ;
        float r = aR[j] + bR;
        float s = 1.0f / (1.0f + expf(-q));
        o[j] = fmaxf(fmaf(p, s, r), 0.f);
    }
    float* op = &g_h[(n0+tx)*FF + c*8];
    *(float4*)op     = make_float4(o[0],o[1],o[2],o[3]);
    *(float4*)(op+4) = make_float4(o[4],o[5],o[6],o[7]);
}

// ---------------- stats / BN finalize ----------------
__global__ void k_clear() {
    int f = threadIdx.x;
    g_sum[f] = 0.0; g_sumsq[f] = 0.0;
}
__global__ __launch_bounds__(256) void k_statsF(int sel) {
    const float* src = sel ? g_agg : g_h;
    int f = threadIdx.x;
    int n0 = blockIdx.x * 64;
    int lim = NN - n0; if (lim > 64) lim = 64;
    double s = 0.0, s2 = 0.0;
    for (int i = 0; i < lim; i++) {
        float v = src[(n0+i)*FF + f];
        s  += (double)v;
        s2 += (double)v * (double)v;
    }
    atomicAdd(&g_sum[f], s);
    atomicAdd(&g_sumsq[f], s2);
}
__global__ void k_finC(const float* __restrict__ gamma, const float* __restrict__ beta) {
    int c = threadIdx.x;   // 32 threads
    double S = 0.0, S2 = 0.0;
#pragma unroll
    for (int t = 0; t < TT; t++) { S += g_sum[c*8+t]; S2 += g_sumsq[c*8+t]; }
    double cnt = (double)NN * TT;
    double mean = S / cnt;
    double var  = S2 / cnt - mean*mean;
    float sc = gamma[c] * rsqrtf((float)var + EPSF);
    float sh = beta[c] - (float)mean * sc;
#pragma unroll
    for (int t = 0; t < TT; t++) { g_scale[c*8+t] = sc; g_shift[c*8+t] = sh; }
}
__global__ void k_finF(const float* __restrict__ gamma, const float* __restrict__ beta) {
    int f = threadIdx.x;   // 256 threads
    double cnt = (double)NN;
    double mean = g_sum[f] / cnt;
    double var  = g_sumsq[f] / cnt - mean*mean;
    float sc = gamma[f] * rsqrtf((float)var + EPSF);
    g_scale[f] = sc;
    g_shift[f] = beta[f] - (float)mean * sc;
}
__global__ void k_coloff(const float* __restrict__ W) {
    int fo = threadIdx.x;  // 256
    float a = 0.f;
    for (int fi = 0; fi < FF; fi++) a = fmaf(g_shift[fi], W[fi*FF + fo], a);
    g_coloff[fo] = a;
}

// ---------------- SGEMM: g_gm = affine(g_h) @ W + coloff ----------------
__global__ __launch_bounds__(256) void k_gemm(const float* __restrict__ W) {
    __shared__ float As[8][132];
    __shared__ float Bs[8][128];
    __shared__ float ssh[256];
    int tid = threadIdx.x;
    ssh[tid] = g_scale[tid];
    int bm = blockIdx.x * 128;
    int bn = blockIdx.y * 128;
    int arow = tid >> 1;
    int acol = (tid & 1) * 4;
    int brow = tid >> 5;
    int bcol = (tid & 31) * 4;
    int tx = tid & 15, ty = tid >> 4;
    float acc[8][8];
#pragma unroll
    for (int i = 0; i < 8; i++)
#pragma unroll
        for (int j = 0; j < 8; j++) acc[i][j] = 0.f;
    __syncthreads();
    for (int k0 = 0; k0 < FF; k0 += 8) {
        float4 av = make_float4(0.f,0.f,0.f,0.f);
        int gr = bm + arow;
        if (gr < NN) av = *(const float4*)&g_h[gr*FF + k0 + acol];
        av.x *= ssh[k0+acol];   av.y *= ssh[k0+acol+1];
        av.z *= ssh[k0+acol+2]; av.w *= ssh[k0+acol+3];
        float4 bv = *(const float4*)&W[(k0+brow)*FF + bn + bcol];
        As[acol+0][arow] = av.x;
        As[acol+1][arow] = av.y;
        As[acol+2][arow] = av.z;
        As[acol+3][arow] = av.w;
        *(float4*)&Bs[brow][bcol] = bv;
        __syncthreads();
#pragma unroll
        for (int k = 0; k < 8; k++) {
            float a[8], b[8];
            *(float4*)&a[0] = *(const float4*)&As[k][ty*8];
            *(float4*)&a[4] = *(const float4*)&As[k][ty*8+4];
            *(float4*)&b[0] = *(const float4*)&Bs[k][tx*8];
            *(float4*)&b[4] = *(const float4*)&Bs[k][tx*8+4];
#pragma unroll
            for (int i = 0; i < 8; i++)
#pragma unroll
                for (int j = 0; j < 8; j++)
                    acc[i][j] = fmaf(a[i], b[j], acc[i][j]);
        }
        __syncthreads();
    }
    float coff[8];
#pragma unroll
    for (int j = 0; j < 8; j++) coff[j] = g_coloff[bn + tx*8 + j];
#pragma unroll
    for (int i = 0; i < 8; i++) {
        int row = bm + ty*8 + i;
        if (row < NN) {
            float* cp = &g_gm[row*FF + bn + tx*8];
            *(float4*)cp     = make_float4(acc[i][0]+coff[0], acc[i][1]+coff[1],
                                           acc[i][2]+coff[2], acc[i][3]+coff[3]);
            *(float4*)(cp+4) = make_float4(acc[i][4]+coff[4], acc[i][5]+coff[5],
                                           acc[i][6]+coff[6], acc[i][7]+coff[7]);
        }
    }
}

// ---------------- GCN aggregation (CSR gather) ----------------
__global__ __launch_bounds__(256) void k_agg(const float* __restrict__ bias) {
    int n = blockIdx.x;
    int f = threadIdx.x;
    float dn = g_dinv[n];
    float acc = g_gm[n*FF + f] * dn;     // self-loop (×dn again below)
    int beg = g_rowptr[n], end = g_rowptr[n+1];
    for (int j = beg; j < end; j++) {
        int s   = g_cols[j];
        float w = g_wsrc[j];
        acc = fmaf(w, g_gm[s*FF + f], acc);
    }
    g_agg[n*FF + f] = fmaf(acc, dn, bias[f]);
}

// ---------------- combine: BN2 affine + fused residual, in-place on x ----
__global__ __launch_bounds__(256) void k_combine(const float* __restrict__ rW,
                                                 const float* __restrict__ rb,
                                                 int do_relu) {
    __shared__ float xs[8*FF];
    __shared__ float wsh[CH*CH];   // wsh[cc*32+c] = rW[c][cc]
    __shared__ float rbs[CH];
    int tid = threadIdx.x;
    int n0 = blockIdx.x * 8;
    for (int i = tid; i < CH*CH; i += 256) wsh[(i & 31)*CH + (i >> 5)] = rW[i];
    if (tid < CH) rbs[tid] = rb[tid];
    for (int i = tid; i < 8*FF; i += 256) xs[i] = g_x[n0*FF + i];
    __syncthreads();
    int nb = tid >> 5, c = tid & 31;
    float acc[8];
#pragma unroll
    for (int j = 0; j < 8; j++) acc[j] = rbs[c];
    const float* xb = &xs[nb*FF];
#pragma unroll
    for (int cc = 0; cc < 32; cc++) {
        float w = wsh[cc*CH + c];
        float4 v0 = *(const float4*)&xb[cc*8];
        float4 v1 = *(const float4*)&xb[cc*8+4];
        acc[0] = fmaf(w, v0.x, acc[0]); acc[1] = fmaf(w, v0.y, acc[1]);
        acc[2] = fmaf(w, v0.z, acc[2]); acc[3] = fmaf(w, v0.w, acc[3]);
        acc[4] = fmaf(w, v1.x, acc[4]); acc[5] = fmaf(w, v1.y, acc[5]);
        acc[6] = fmaf(w, v1.z, acc[6]); acc[7] = fmaf(w, v1.w, acc[7]);
    }
    int n = n0 + nb;
    float sc = g_scale[c*8], sh = g_shift[c*8];
    const float* hp = &g_h[n*FF + c*8];
    float4 h0 = *(const float4*)hp;
    float4 h1 = *(const float4*)(hp+4);
    float o[8];
    o[0] = acc[0] + fmaf(sc, h0.x, sh); o[1] = acc[1] + fmaf(sc, h0.y, sh);
    o[2] = acc[2] + fmaf(sc, h0.z, sh); o[3] = acc[3] + fmaf(sc, h0.w, sh);
    o[4] = acc[4] + fmaf(sc, h1.x, sh); o[5] = acc[5] + fmaf(sc, h1.y, sh);
    o[6] = acc[6] + fmaf(sc, h1.z, sh); o[7] = acc[7] + fmaf(sc, h1.w, sh);
    if (do_relu) {
#pragma unroll
        for (int j = 0; j < 8; j++) o[j] = fmaxf(o[j], 0.f);
    }
    float* op = &g_x[n*FF + c*8];
    *(float4*)op     = make_float4(o[0],o[1],o[2],o[3]);
    *(float4*)(op+4) = make_float4(o[4],o[5],o[6],o[7]);
}

// ---------------- graph pooling ----------------
__global__ void k_pool_init() {
    int i = blockIdx.x*blockDim.x + threadIdx.x;
    if (i < GG*CH) { g_psum[i] = 0.f; g_pmax[i] = 0x007FFFFFu; }  // fmap(-inf)
    if (i < GG) g_pcnt[i] = 0;
}
__global__ __launch_bounds__(256) void k_pool(const int* __restrict__ graphs) {
    int idx = blockIdx.x*blockDim.x + threadIdx.x;
    if (idx >= NN*CH) return;
    int n = idx >> 5, c = idx & 31;
    float v = g_x[n*FF + c*8 + 7];   // x[:, c, T-1]
    int g = graphs[n];
    atomicAdd(&g_psum[g*CH + c], v);
    atomicMax(&g_pmax[g*CH + c], fmap(v));
    if (c == 0) atomicAdd(&g_pcnt[g], 1);
}

// ---------------- output MLP ----------------
__global__ __launch_bounds__(ENDW) void k_mlp1(const float* __restrict__ W1,
                                               const float* __restrict__ b1) {
    __shared__ float xg[3*CH];
    int g = blockIdx.x, tid = threadIdx.x;
    if (tid < CH) {
        int cnt = g_pcnt[g];
        float s = g_psum[g*CH + tid];
        float mean = s / fmaxf((float)cnt, 1.0f);
        float mx = (cnt > 0) ? funmap(g_pmax[g*CH + tid]) : 0.f;
        xg[tid]      = mean;
        xg[CH+tid]   = mx;
        xg[2*CH+tid] = s;
    }
    __syncthreads();
    float a = b1[tid];
    for (int k = 0; k < 3*CH; k++) a = fmaf(xg[k], W1[k*ENDW + tid], a);
    g_m1[g*ENDW + tid] = fmaxf(a, 0.f);
}
__global__ __launch_bounds__(64) void k_mlp2(const float* __restrict__ W2,
                                             const float* __restrict__ b2) {
    int g = blockIdx.x, j = threadIdx.x;
    float a = b2[j];
    for (int k = 0; k < ENDW; k++) a = fmaf(g_m1[g*ENDW + k], W2[k*64 + j], a);
    g_m2[g*64 + j] = fmaxf(a, 0.f);
}
__global__ __launch_bounds__(64) void k_mlp3(const float* __restrict__ W3,
                                             const float* __restrict__ b3,
                                             float* __restrict__ out) {
    int g = threadIdx.x;
    float a = b3[0];
    for (int k = 0; k < 64; k++) a = fmaf(g_m2[g*64 + k], W3[k], a);
    out[g] = a;
}

// ---------------- launch ----------------
extern "C" void kernel_launch(void* const* d_in, const int* in_sizes, int n_in,
                              void* d_out, int out_size) {
    const float* X     = (const float*)d_in[0];
    const int*   ei    = (const int*)d_in[1];
    const int*   graphs= (const int*)d_in[2];
    const float* W_in  = (const float*)d_in[3];
    const float* b_in  = (const float*)d_in[4];
    const float* res_W = (const float*)d_in[5];
    const float* res_b = (const float*)d_in[6];
    const float* g1_W  = (const float*)d_in[7];
    const float* g1_b  = (const float*)d_in[8];
    const float* bn0_g = (const float*)d_in[9];
    const float* bn0_b = (const float*)d_in[10];
    const float* gcn_W = (const float*)d_in[11];
    const float* gcn_b = (const float*)d_in[12];
    const float* bn1_g = (const float*)d_in[13];
    const float* bn1_b = (const float*)d_in[14];
    const float* g2_W  = (const float*)d_in[15];
    const float* g2_b  = (const float*)d_in[16];
    const float* bn2_g = (const float*)d_in[17];
    const float* bn2_b = (const float*)d_in[18];
    const float* oW1   = (const float*)d_in[19];
    const float* ob1   = (const float*)d_in[20];
    const float* oW2   = (const float*)d_in[21];
    const float* ob2   = (const float*)d_in[22];
    const float* oW3   = (const float*)d_in[23];
    const float* ob3   = (const float*)d_in[24];
    float* out = (float*)d_out;

    const int* src = ei;
    const int* dst = ei + EE;

    // CSR build
    k_zero_indeg<<<(NN+255)/256, 256>>>();
    k_count<<<(EE+255)/256, 256>>>(dst);
    k_dinv<<<(NN+255)/256, 256>>>();
    k_scanA<<<(NN+1023)/1024, 1024>>>();
    k_scanB<<<1, 1>>>((NN+1023)/1024);
    k_scanC<<<(NN+255)/256, 256>>>();
    k_fill<<<(EE+255)/256, 256>>>(src, dst);

    // input conv
    k_inconv<<<NN, 256>>>(X, W_in, b_in);

    const int GB = NN / 8;          // 6250 gated-conv blocks
    const int SB = (NN + 63) / 64;  // stats blocks

    for (int i = 0; i < 2; i++) {
        // gated conv 1 (input: g_x, no affine)
        k_gated<<<GB, 256>>>(0, 0, g1_W + i*9216, g1_b + i*96);
        // bn0 (per channel) -> affine for GEMM A-load
        k_clear<<<1, 256>>>();
        k_statsF<<<SB, 256>>>(0);
        k_finC<<<1, 32>>>(bn0_g + i*32, bn0_b + i*32);
        // GEMM with folded affine
        k_coloff<<<1, 256>>>(gcn_W + i*65536);
        k_gemm<<<dim3((NN+127)/128, 2), 256>>>(gcn_W + i*65536);
        // aggregation
        k_agg<<<NN, 256>>>(gcn_b + i*256);
        // bn1 (per feature) -> affine for gated conv 2 load
        k_clear<<<1, 256>>>();
        k_statsF<<<SB, 256>>>(1);
        k_finF<<<1, 256>>>(bn1_g + i*256, bn1_b + i*256);
        // gated conv 2 (input: g_agg with bn1 affine)
        k_gated<<<GB, 256>>>(1, 1, g2_W + i*9216, g2_b + i*96);
        // bn2 (per channel)
        k_clear<<<1, 256>>>();
        k_statsF<<<SB, 256>>>(0);
        k_finC<<<1, 32>>>(bn2_g + i*32, bn2_b + i*32);
        // combine: bn2(h) + residual(x), relu on first layer, write g_x
        k_combine<<<GB, 256>>>(res_W + i*1024, res_b + i*32, (i == 0) ? 1 : 0);
    }

    // pooling + MLP
    k_pool_init<<<(GG*CH+255)/256, 256>>>();
    k_pool<<<(NN*CH+255)/256, 256>>>(graphs);
    k_mlp1<<<GG, ENDW>>>(oW1, ob1);
    k_mlp2<<<GG, 64>>>(oW2, ob2);
    k_mlp3<<<1, 64>>>(oW3, ob3, out);
}

// round 16
// speedup vs baseline: 1.0744x; 1.0744x over previous
#include <cuda_runtime.h>
#include <cuda_fp16.h>
#include <mma.h>
#include <math.h>
#include <stdint.h>

using namespace nvcuda;

#define NN   50000
#define EE   400000
#define TT   8
#define CINN 16
#define CH   32
#define FF   256
#define GG   64
#define ENDW 128
#define EPSF 1e-5f

// ---------------- scratch (device globals; no allocation) ----------------
__device__ float  g_x[NN*FF];
__device__ float  g_h[NN*FF];
__device__ float  g_gm[NN*FF];
__device__ float  g_agg[NN*FF];
__device__ float  g_dinv[NN];
__device__ int    g_indeg[NN];
__device__ int    g_rowptr[NN+1];
__device__ int    g_cursor[NN];
__device__ int    g_cols[EE];
__device__ float  g_wsrc[EE];
__device__ int    g_bsum[64];
__device__ double g_sum[FF];
__device__ double g_sumsq[FF];
__device__ float  g_scale[FF];
__device__ float  g_shift[FF];
__device__ float  g_coloff[FF];
__device__ __half g_Bh[FF*FF];   // B'[k][n] = hi(scale[k]*W[k][n])  (fp16)
__device__ __half g_Bl[FF*FF];   // lo residual (fp16)
__device__ float    g_psum[GG*CH];
__device__ unsigned g_pmax[GG*CH];
__device__ int      g_pcnt[GG];
__device__ float  g_m1[GG*ENDW];
__device__ float  g_m2[GG*64];

__device__ __forceinline__ unsigned fmap(float v) {
    unsigned u = __float_as_uint(v);
    return (u & 0x80000000u) ? ~u : (u | 0x80000000u);
}
__device__ __forceinline__ float funmap(unsigned u) {
    return (u & 0x80000000u) ? __uint_as_float(u & 0x7fffffffu) : __uint_as_float(~u);
}

// ---------------- input conv (1x1, CIN=16 -> C=32) ----------------
__global__ __launch_bounds__(256) void k_inconv(const float* __restrict__ X,
                                                const float* __restrict__ Wi,
                                                const float* __restrict__ bi) {
    __shared__ float xs[CINN*TT];
    __shared__ float wsh[CH*CINN];
    __shared__ float bsh[CH];
    int n = blockIdx.x, tid = threadIdx.x;
    if (tid < CINN*TT) xs[tid] = X[n*CINN*TT + tid];
    if (tid < CH) bsh[tid] = bi[tid];
    for (int i = tid; i < CH*CINN; i += 256) wsh[i] = Wi[i];
    __syncthreads();
    int c = tid >> 3, t = tid & 7;
    float a = bsh[c];
#pragma unroll
    for (int ci = 0; ci < CINN; ci++) a = fmaf(wsh[c*CINN+ci], xs[ci*TT+t], a);
    g_x[n*FF + tid] = a;
}

// ---------------- degree / CSR build ----------------
__global__ void k_zero_indeg() {
    int i = blockIdx.x*blockDim.x + threadIdx.x;
    if (i < NN) g_indeg[i] = 0;
}
__global__ void k_count(const int* __restrict__ dst) {
    int e = blockIdx.x*blockDim.x + threadIdx.x;
    if (e < EE) atomicAdd(&g_indeg[dst[e]], 1);
}
__global__ void k_dinv() {
    int i = blockIdx.x*blockDim.x + threadIdx.x;
    if (i < NN) g_dinv[i] = rsqrtf(1.0f + (float)g_indeg[i]);
}
__global__ __launch_bounds__(1024) void k_scanA() {
    __shared__ int sh[1024];
    int i = blockIdx.x*1024 + threadIdx.x;
    int v = (i < NN) ? g_indeg[i] : 0;
    sh[threadIdx.x] = v;
    __syncthreads();
    for (int off = 1; off < 1024; off <<= 1) {
        int t = (threadIdx.x >= off) ? sh[threadIdx.x-off] : 0;
        __syncthreads();
        sh[threadIdx.x] += t;
        __syncthreads();
    }
    if (i < NN) g_rowptr[i] = sh[threadIdx.x] - v;
    if (threadIdx.x == 1023) g_bsum[blockIdx.x] = sh[1023];
}
__global__ void k_scanB(int nblk) {
    int acc = 0;
    for (int b = 0; b < nblk; b++) { int t = g_bsum[b]; g_bsum[b] = acc; acc += t; }
    g_rowptr[NN] = acc;
}
__global__ void k_scanC() {
    int i = blockIdx.x*blockDim.x + threadIdx.x;
    if (i < NN) {
        int v = g_rowptr[i] + g_bsum[i >> 10];
        g_rowptr[i] = v;
        g_cursor[i] = v;
    }
}
__global__ void k_fill(const int* __restrict__ src, const int* __restrict__ dst) {
    int e = blockIdx.x*blockDim.x + threadIdx.x;
    if (e < EE) {
        int d = dst[e];
        int p = atomicAdd(&g_cursor[d], 1);
        int s = src[e];
        g_cols[p] = s;
        g_wsrc[p] = g_dinv[s];
    }
}

// ---------------- gated conv (C=32->32, k=3, pad=1), 8 nodes/block ----------------
__global__ __launch_bounds__(256) void k_gated(int src_sel, int use_affine,
                                               const float* __restrict__ W3,
                                               const float* __restrict__ b3) {
    __shared__ float ws[9216];
    __shared__ float xs[8*330];
    __shared__ float bsh[96];
    const float* in = src_sel ? g_agg : g_x;
    int tid = threadIdx.x;
    for (int i = tid; i < 9216; i += 256) {
        int k = i % 3, cc = (i/3) & 31, c = (i/96) & 31, conv = i / 3072;
        ws[(cc*3+k)*96 + conv*32 + c] = W3[i];
    }
    if (tid < 96) bsh[tid] = b3[tid];
    {
        int nb = tid >> 5, cc = tid & 31;
        xs[nb*330 + cc*10]     = 0.f;
        xs[nb*330 + cc*10 + 9] = 0.f;
    }
    int n0 = blockIdx.x * 8;
    for (int i = tid; i < 8*FF; i += 256) {
        int nb = i >> 8, f = i & 255;
        float v = in[(n0+nb)*FF + f];
        if (use_affine) v = fmaf(v, g_scale[f], g_shift[f]);
        xs[nb*330 + (f>>3)*10 + 1 + (f&7)] = v;
    }
    __syncthreads();
    int tx = tid & 7, c = tid >> 3;
    float aP[8], aQ[8], aR[8];
#pragma unroll
    for (int j = 0; j < 8; j++) { aP[j] = 0.f; aQ[j] = 0.f; aR[j] = 0.f; }
    const float* xb = &xs[tx*330];
    for (int cc = 0; cc < 32; cc++) {
        float xr[10];
#pragma unroll
        for (int m = 0; m < 10; m++) xr[m] = xb[cc*10+m];
#pragma unroll
        for (int k = 0; k < 3; k++) {
            int kk = (cc*3+k)*96;
            float wP = ws[kk + c];
            float wQ = ws[kk + 32 + c];
            float wR = ws[kk + 64 + c];
#pragma unroll
            for (int j = 0; j < 8; j++) {
                aP[j] = fmaf(wP, xr[j+k], aP[j]);
                aQ[j] = fmaf(wQ, xr[j+k], aQ[j]);
                aR[j] = fmaf(wR, xr[j+k], aR[j]);
            }
        }
    }
    float bP = bsh[c], bQ = bsh[32+c], bR = bsh[64+c];
    float o[8];
#pragma unroll
    for (int j = 0; j < 8; j++) {
        float p = aP[j] + bP;
        float q = aQ[j] + bQ;
        float r = aR[j] + bR;
        float s = 1.0f / (1.0f + expf(-q));
        o[j] = fmaxf(fmaf(p, s, r), 0.f);
    }
    float* op = &g_h[(n0+tx)*FF + c*8];
    *(float4*)op     = make_float4(o[0],o[1],o[2],o[3]);
    *(float4*)(op+4) = make_float4(o[4],o[5],o[6],o[7]);
}

// ---------------- stats / BN finalize ----------------
__global__ void k_clear() {
    int f = threadIdx.x;
    g_sum[f] = 0.0; g_sumsq[f] = 0.0;
}
__global__ __launch_bounds__(256) void k_statsF(int sel) {
    const float* src = sel ? g_agg : g_h;
    int f = threadIdx.x;
    int n0 = blockIdx.x * 64;
    int lim = NN - n0; if (lim > 64) lim = 64;
    double s = 0.0, s2 = 0.0;
    for (int i = 0; i < lim; i++) {
        float v = src[(n0+i)*FF + f];
        s  += (double)v;
        s2 += (double)v * (double)v;
    }
    atomicAdd(&g_sum[f], s);
    atomicAdd(&g_sumsq[f], s2);
}
__global__ void k_finC(const float* __restrict__ gamma, const float* __restrict__ beta) {
    int c = threadIdx.x;   // 32 threads
    double S = 0.0, S2 = 0.0;
#pragma unroll
    for (int t = 0; t < TT; t++) { S += g_sum[c*8+t]; S2 += g_sumsq[c*8+t]; }
    double cnt = (double)NN * TT;
    double mean = S / cnt;
    double var  = S2 / cnt - mean*mean;
    float sc = gamma[c] * rsqrtf((float)var + EPSF);
    float sh = beta[c] - (float)mean * sc;
#pragma unroll
    for (int t = 0; t < TT; t++) { g_scale[c*8+t] = sc; g_shift[c*8+t] = sh; }
}
__global__ void k_finF(const float* __restrict__ gamma, const float* __restrict__ beta) {
    int f = threadIdx.x;   // 256 threads
    double cnt = (double)NN;
    double mean = g_sum[f] / cnt;
    double var  = g_sumsq[f] / cnt - mean*mean;
    float sc = gamma[f] * rsqrtf((float)var + EPSF);
    g_scale[f] = sc;
    g_shift[f] = beta[f] - (float)mean * sc;
}
__global__ void k_coloff(const float* __restrict__ W) {
    int fo = threadIdx.x;  // 256
    float a = 0.f;
    for (int fi = 0; fi < FF; fi++) a = fmaf(g_shift[fi], W[fi*FF + fo], a);
    g_coloff[fo] = a;
}

// ---------------- B prep: B'[k][n] = scale[k]*W[k][n], split fp16 hi/lo ------
__global__ __launch_bounds__(256) void k_prepB(const float* __restrict__ W) {
    int k = blockIdx.x;    // FF blocks
    int n = threadIdx.x;   // FF threads
    float v = g_scale[k] * W[k*FF + n];
    __half h = __float2half_rn(v);
    __half l = __float2half_rn(v - __half2float(h));
    g_Bh[k*FF + n] = h;
    g_Bl[k*FF + n] = l;
}

// ---------------- WMMA fp16-split GEMM: g_gm = g_h @ B' + coloff -------------
// Block tile 128x128, 8 warps (2x4), warp tile 64x32, K-step 32, 3-product split.
__global__ __launch_bounds__(256) void k_gemm_wmma() {
    __shared__ __align__(16) __half Ah[128][40];
    __shared__ __align__(16) __half Al[128][40];
    __shared__ __align__(16) __half Bh[32][136];
    __shared__ __align__(16) __half Bl[32][136];
    __shared__ __align__(16) float  scr[8][16][20];

    int tid = threadIdx.x, wid = tid >> 5, lane = tid & 31;
    int bm = blockIdx.x * 128;
    int bn = blockIdx.y * 128;
    int wm = (wid >> 2) * 64;   // 0 or 64
    int wn = (wid & 3) * 32;    // 0,32,64,96

    wmma::fragment<wmma::accumulator, 16, 16, 16, float> acc[4][2];
#pragma unroll
    for (int i = 0; i < 4; i++)
#pragma unroll
        for (int j = 0; j < 2; j++) wmma::fill_fragment(acc[i][j], 0.0f);

    int ar = tid >> 1;             // A row 0..127
    int acb = (tid & 1) * 16;      // A col base 0 or 16
    int brr = tid >> 3;            // B row 0..31
    int bnb = (tid & 7) * 16;      // B col base 0..112

    for (int k0 = 0; k0 < FF; k0 += 32) {
        // ---- load A tile: 128 x 32 floats -> fp16 hi/lo ----
#pragma unroll
        for (int q = 0; q < 4; q++) {
            int cc = acb + q * 4;
            float4 a = make_float4(0.f, 0.f, 0.f, 0.f);
            if (bm + ar < NN) a = *(const float4*)&g_h[(bm + ar)*FF + k0 + cc];
            __half hx = __float2half_rn(a.x), hy = __float2half_rn(a.y);
            __half hz = __float2half_rn(a.z), hw = __float2half_rn(a.w);
            __half lx = __float2half_rn(a.x - __half2float(hx));
            __half ly = __float2half_rn(a.y - __half2float(hy));
            __half lz = __float2half_rn(a.z - __half2float(hz));
            __half lw = __float2half_rn(a.w - __half2float(hw));
            *(half2*)&Ah[ar][cc]     = __halves2half2(hx, hy);
            *(half2*)&Ah[ar][cc + 2] = __halves2half2(hz, hw);
            *(half2*)&Al[ar][cc]     = __halves2half2(lx, ly);
            *(half2*)&Al[ar][cc + 2] = __halves2half2(lz, lw);
        }
        // ---- load B tile: 32 x 128 halves (pre-split) ----
        {
            const uint4* ph = (const uint4*)&g_Bh[(k0 + brr)*FF + bn + bnb];
            const uint4* pl = (const uint4*)&g_Bl[(k0 + brr)*FF + bn + bnb];
            uint4 v0 = ph[0], v1 = ph[1];
            uint4 w0 = pl[0], w1 = pl[1];
            *(uint4*)&Bh[brr][bnb]     = v0;
            *(uint4*)&Bh[brr][bnb + 8] = v1;
            *(uint4*)&Bl[brr][bnb]     = w0;
            *(uint4*)&Bl[brr][bnb + 8] = w1;
        }
        __syncthreads();
        // ---- compute: 2 k-subtiles of 16 ----
#pragma unroll
        for (int ks = 0; ks < 2; ks++) {
            wmma::fragment<wmma::matrix_a, 16, 16, 16, __half, wmma::row_major> ah[4], al[4];
            wmma::fragment<wmma::matrix_b, 16, 16, 16, __half, wmma::row_major> bh[2], bl[2];
#pragma unroll
            for (int i = 0; i < 4; i++) {
                wmma::load_matrix_sync(ah[i], &Ah[wm + i*16][ks*16], 40);
                wmma::load_matrix_sync(al[i], &Al[wm + i*16][ks*16], 40);
            }
#pragma unroll
            for (int j = 0; j < 2; j++) {
                wmma::load_matrix_sync(bh[j], &Bh[ks*16][wn + j*16], 136);
                wmma::load_matrix_sync(bl[j], &Bl[ks*16][wn + j*16], 136);
            }
#pragma unroll
            for (int i = 0; i < 4; i++)
#pragma unroll
                for (int j = 0; j < 2; j++) {
                    wmma::mma_sync(acc[i][j], ah[i], bh[j], acc[i][j]);
                    wmma::mma_sync(acc[i][j], ah[i], bl[j], acc[i][j]);
                    wmma::mma_sync(acc[i][j], al[i], bh[j], acc[i][j]);
                }
        }
        __syncthreads();
    }

    // ---- epilogue: per-warp scratch, add coloff, guarded store ----
#pragma unroll
    for (int i = 0; i < 4; i++)
#pragma unroll
        for (int j = 0; j < 2; j++) {
            wmma::store_matrix_sync(&scr[wid][0][0], acc[i][j], 20, wmma::mem_row_major);
            __syncwarp();
#pragma unroll
            for (int e = 0; e < 8; e++) {
                int idx = lane + e * 32;
                int rr = idx >> 4, cc2 = idx & 15;
                int m = bm + wm + i*16 + rr;
                if (m < NN) {
                    int nc = bn + wn + j*16 + cc2;
                    g_gm[m*FF + nc] = scr[wid][rr][cc2] + g_coloff[nc];
                }
            }
            __syncwarp();
        }
}

// ---------------- GCN aggregation (CSR gather) ----------------
__global__ __launch_bounds__(256) void k_agg(const float* __restrict__ bias) {
    int n = blockIdx.x;
    int f = threadIdx.x;
    float dn = g_dinv[n];
    float acc = g_gm[n*FF + f] * dn;
    int beg = g_rowptr[n], end = g_rowptr[n+1];
    for (int j = beg; j < end; j++) {
        int s   = g_cols[j];
        float w = g_wsrc[j];
        acc = fmaf(w, g_gm[s*FF + f], acc);
    }
    g_agg[n*FF + f] = fmaf(acc, dn, bias[f]);
}

// ---------------- combine: BN2 affine + fused residual, in-place on x ----
__global__ __launch_bounds__(256) void k_combine(const float* __restrict__ rW,
                                                 const float* __restrict__ rb,
                                                 int do_relu) {
    __shared__ float xs[8*FF];
    __shared__ float wsh[CH*CH];
    __shared__ float rbs[CH];
    int tid = threadIdx.x;
    int n0 = blockIdx.x * 8;
    for (int i = tid; i < CH*CH; i += 256) wsh[(i & 31)*CH + (i >> 5)] = rW[i];
    if (tid < CH) rbs[tid] = rb[tid];
    for (int i = tid; i < 8*FF; i += 256) xs[i] = g_x[n0*FF + i];
    __syncthreads();
    int nb = tid >> 5, c = tid & 31;
    float acc[8];
#pragma unroll
    for (int j = 0; j < 8; j++) acc[j] = rbs[c];
    const float* xb = &xs[nb*FF];
#pragma unroll
    for (int cc = 0; cc < 32; cc++) {
        float w = wsh[cc*CH + c];
        float4 v0 = *(const float4*)&xb[cc*8];
        float4 v1 = *(const float4*)&xb[cc*8+4];
        acc[0] = fmaf(w, v0.x, acc[0]); acc[1] = fmaf(w, v0.y, acc[1]);
        acc[2] = fmaf(w, v0.z, acc[2]); acc[3] = fmaf(w, v0.w, acc[3]);
        acc[4] = fmaf(w, v1.x, acc[4]); acc[5] = fmaf(w, v1.y, acc[5]);
        acc[6] = fmaf(w, v1.z, acc[6]); acc[7] = fmaf(w, v1.w, acc[7]);
    }
    int n = n0 + nb;
    float sc = g_scale[c*8], sh = g_shift[c*8];
    const float* hp = &g_h[n*FF + c*8];
    float4 h0 = *(const float4*)hp;
    float4 h1 = *(const float4*)(hp+4);
    float o[8];
    o[0] = acc[0] + fmaf(sc, h0.x, sh); o[1] = acc[1] + fmaf(sc, h0.y, sh);
    o[2] = acc[2] + fmaf(sc, h0.z, sh); o[3] = acc[3] + fmaf(sc, h0.w, sh);
    o[4] = acc[4] + fmaf(sc, h1.x, sh); o[5] = acc[5] + fmaf(sc, h1.y, sh);
    o[6] = acc[6] + fmaf(sc, h1.z, sh); o[7] = acc[7] + fmaf(sc, h1.w, sh);
    if (do_relu) {
#pragma unroll
        for (int j = 0; j < 8; j++) o[j] = fmaxf(o[j], 0.f);
    }
    float* op = &g_x[n*FF + c*8];
    *(float4*)op     = make_float4(o[0],o[1],o[2],o[3]);
    *(float4*)(op+4) = make_float4(o[4],o[5],o[6],o[7]);
}

// ---------------- graph pooling ----------------
__global__ void k_pool_init() {
    int i = blockIdx.x*blockDim.x + threadIdx.x;
    if (i < GG*CH) { g_psum[i] = 0.f; g_pmax[i] = 0x007FFFFFu; }
    if (i < GG) g_pcnt[i] = 0;
}
__global__ __launch_bounds__(256) void k_pool(const int* __restrict__ graphs) {
    int idx = blockIdx.x*blockDim.x + threadIdx.x;
    if (idx >= NN*CH) return;
    int n = idx >> 5, c = idx & 31;
    float v = g_x[n*FF + c*8 + 7];
    int g = graphs[n];
    atomicAdd(&g_psum[g*CH + c], v);
    atomicMax(&g_pmax[g*CH + c], fmap(v));
    if (c == 0) atomicAdd(&g_pcnt[g], 1);
}

// ---------------- output MLP ----------------
__global__ __launch_bounds__(ENDW) void k_mlp1(const float* __restrict__ W1,
                                               const float* __restrict__ b1) {
    __shared__ float xg[3*CH];
    int g = blockIdx.x, tid = threadIdx.x;
    if (tid < CH) {
        int cnt = g_pcnt[g];
        float s = g_psum[g*CH + tid];
        float mean = s / fmaxf((float)cnt, 1.0f);
        float mx = (cnt > 0) ? funmap(g_pmax[g*CH + tid]) : 0.f;
        xg[tid]      = mean;
        xg[CH+tid]   = mx;
        xg[2*CH+tid] = s;
    }
    __syncthreads();
    float a = b1[tid];
    for (int k = 0; k < 3*CH; k++) a = fmaf(xg[k], W1[k*ENDW + tid], a);
    g_m1[g*ENDW + tid] = fmaxf(a, 0.f);
}
__global__ __launch_bounds__(64) void k_mlp2(const float* __restrict__ W2,
                                             const float* __restrict__ b2) {
    int g = blockIdx.x, j = threadIdx.x;
    float a = b2[j];
    for (int k = 0; k < ENDW; k++) a = fmaf(g_m1[g*ENDW + k], W2[k*64 + j], a);
    g_m2[g*64 + j] = fmaxf(a, 0.f);
}
__global__ __launch_bounds__(64) void k_mlp3(const float* __restrict__ W3,
                                             const float* __restrict__ b3,
                                             float* __restrict__ out) {
    int g = threadIdx.x;
    float a = b3[0];
    for (int k = 0; k < 64; k++) a = fmaf(g_m2[g*64 + k], W3[k], a);
    out[g] = a;
}

// ---------------- launch ----------------
extern "C" void kernel_launch(void* const* d_in, const int* in_sizes, int n_in,
                              void* d_out, int out_size) {
    const float* X     = (const float*)d_in[0];
    const int*   ei    = (const int*)d_in[1];
    const int*   graphs= (const int*)d_in[2];
    const float* W_in  = (const float*)d_in[3];
    const float* b_in  = (const float*)d_in[4];
    const float* res_W = (const float*)d_in[5];
    const float* res_b = (const float*)d_in[6];
    const float* g1_W  = (const float*)d_in[7];
    const float* g1_b  = (const float*)d_in[8];
    const float* bn0_g = (const float*)d_in[9];
    const float* bn0_b = (const float*)d_in[10];
    const float* gcn_W = (const float*)d_in[11];
    const float* gcn_b = (const float*)d_in[12];
    const float* bn1_g = (const float*)d_in[13];
    const float* bn1_b = (const float*)d_in[14];
    const float* g2_W  = (const float*)d_in[15];
    const float* g2_b  = (const float*)d_in[16];
    const float* bn2_g = (const float*)d_in[17];
    const float* bn2_b = (const float*)d_in[18];
    const float* oW1   = (const float*)d_in[19];
    const float* ob1   = (const float*)d_in[20];
    const float* oW2   = (const float*)d_in[21];
    const float* ob2   = (const float*)d_in[22];
    const float* oW3   = (const float*)d_in[23];
    const float* ob3   = (const float*)d_in[24];
    float* out = (float*)d_out;

    const int* src = ei;
    const int* dst = ei + EE;

    // CSR build
    k_zero_indeg<<<(NN+255)/256, 256>>>();
    k_count<<<(EE+255)/256, 256>>>(dst);
    k_dinv<<<(NN+255)/256, 256>>>();
    k_scanA<<<(NN+1023)/1024, 1024>>>();
    k_scanB<<<1, 1>>>((NN+1023)/1024);
    k_scanC<<<(NN+255)/256, 256>>>();
    k_fill<<<(EE+255)/256, 256>>>(src, dst);

    // input conv
    k_inconv<<<NN, 256>>>(X, W_in, b_in);

    const int GB = NN / 8;
    const int SB = (NN + 63) / 64;
    const dim3 GEMMG((NN + 127) / 128, 2);

    for (int i = 0; i < 2; i++) {
        k_gated<<<GB, 256>>>(0, 0, g1_W + i*9216, g1_b + i*96);
        k_clear<<<1, 256>>>();
        k_statsF<<<SB, 256>>>(0);
        k_finC<<<1, 32>>>(bn0_g + i*32, bn0_b + i*32);
        k_coloff<<<1, 256>>>(gcn_W + i*65536);
        k_prepB<<<FF, FF>>>(gcn_W + i*65536);
        k_gemm_wmma<<<GEMMG, 256>>>();
        k_agg<<<NN, 256>>>(gcn_b + i*256);
        k_clear<<<1, 256>>>();
        k_statsF<<<SB, 256>>>(1);
        k_finF<<<1, 256>>>(bn1_g + i*256, bn1_b + i*256);
        k_gated<<<GB, 256>>>(1, 1, g2_W + i*9216, g2_b + i*96);
        k_clear<<<1, 256>>>();
        k_statsF<<<SB, 256>>>(0);
        k_finC<<<1, 32>>>(bn2_g + i*32, bn2_b + i*32);
        k_combine<<<GB, 256>>>(res_W + i*1024, res_b + i*32, (i == 0) ? 1 : 0);
    }

    k_pool_init<<<(GG*CH+255)/256, 256>>>();
    k_pool<<<(NN*CH+255)/256, 256>>>(graphs);
    k_mlp1<<<GG, ENDW>>>(oW1, ob1);
    k_mlp2<<<GG, 64>>>(oW2, ob2);
    k_mlp3<<<1, 64>>>(oW3, ob3, out);
}